// round 4
// baseline (speedup 1.0000x reference)
#include <cuda_runtime.h>
#include <math.h>

#define HT 128
#define WT 128
#define HS 256
#define WS 256
#define NC 32
#define NV 3
#define ND 48
#define NPIX (HT * WT)
#define VSTRIDE (ND * NPIX)

// Static scratch (no allocs allowed)
__device__ float  d_featT[NV * HS * WS * NC];   // (v,y,x,c) channel-last, ~25MB
__device__ float4 d_wgt[NV * ND * NPIX];        // bilinear weights  w00,w01,w10,w11
__device__ int4   d_off4[NV * ND * NPIX];       // absolute byte offsets of 4 taps
__device__ float  d_cost[ND * NPIX];            // cost volume (d, pix)
__device__ float  d_proj[NV * 12];

// ---------------------------------------------------------------------------
// Kernel 1: projection matrices  proj_v = (Ks_v E_v[:3,:]) inv([Kt Et[:3,:];0001])
// ---------------------------------------------------------------------------
__global__ void setup_kernel(const float* __restrict__ src_exts,
                             const float* __restrict__ src_ints,
                             const float* __restrict__ tar_exts,
                             const float* __restrict__ tar_ints)
{
    if (threadIdx.x != 0) return;
    double T[4][4], inv[4][4];
    for (int i = 0; i < 3; i++)
        for (int j = 0; j < 4; j++) {
            double s = 0.0;
            for (int k = 0; k < 3; k++)
                s += (double)tar_ints[i * 3 + k] * (double)tar_exts[k * 4 + j];
            T[i][j] = s;
        }
    T[3][0] = 0.0; T[3][1] = 0.0; T[3][2] = 0.0; T[3][3] = 1.0;
    for (int i = 0; i < 4; i++)
        for (int j = 0; j < 4; j++) inv[i][j] = (i == j) ? 1.0 : 0.0;
    for (int col = 0; col < 4; col++) {
        int piv = col; double best = fabs(T[col][col]);
        for (int r = col + 1; r < 4; r++) {
            double a = fabs(T[r][col]);
            if (a > best) { best = a; piv = r; }
        }
        if (piv != col)
            for (int j = 0; j < 4; j++) {
                double t = T[col][j]; T[col][j] = T[piv][j]; T[piv][j] = t;
                t = inv[col][j]; inv[col][j] = inv[piv][j]; inv[piv][j] = t;
            }
        double p = 1.0 / T[col][col];
        for (int j = 0; j < 4; j++) { T[col][j] *= p; inv[col][j] *= p; }
        for (int r = 0; r < 4; r++)
            if (r != col) {
                double f = T[r][col];
                for (int j = 0; j < 4; j++) {
                    T[r][j] -= f * T[col][j];
                    inv[r][j] -= f * inv[col][j];
                }
            }
    }
    for (int v = 0; v < NV; v++) {
        const float* K = src_ints + v * 9;
        const float* E = src_exts + v * 16;
        double A[3][4];
        for (int i = 0; i < 3; i++)
            for (int j = 0; j < 4; j++) {
                double s = 0.0;
                for (int k = 0; k < 3; k++)
                    s += (double)K[i * 3 + k] * (double)E[k * 4 + j];
                A[i][j] = s;
            }
        for (int i = 0; i < 3; i++)
            for (int j = 0; j < 4; j++) {
                double s = 0.0;
                for (int k = 0; k < 4; k++) s += A[i][k] * inv[k][j];
                d_proj[v * 12 + i * 4 + j] = (float)s;
            }
    }
}

// ---------------------------------------------------------------------------
// Kernel 2: transpose (V,C,H,W) -> (V,H,W,C), 4 pixels per thread, all 128-bit
// ---------------------------------------------------------------------------
__global__ void transpose_kernel(const float* __restrict__ src)
{
    int idx = blockIdx.x * blockDim.x + threadIdx.x;      // over NV*HS*WS/4
    if (idx >= NV * HS * WS / 4) return;
    int x4 = (idx & (WS / 4 - 1)) * 4;
    int y  = (idx >> 6) & (HS - 1);
    int v  = idx >> 14;
    const float* in = src + ((size_t)(v * NC) * HS + y) * WS + x4;
    float* out = d_featT + ((size_t)(v * HS + y) * WS + x4) * NC;

#pragma unroll
    for (int c4 = 0; c4 < NC / 4; c4++) {
        float4 L0 = *reinterpret_cast<const float4*>(in + (size_t)(c4 * 4 + 0) * HS * WS);
        float4 L1 = *reinterpret_cast<const float4*>(in + (size_t)(c4 * 4 + 1) * HS * WS);
        float4 L2 = *reinterpret_cast<const float4*>(in + (size_t)(c4 * 4 + 2) * HS * WS);
        float4 L3 = *reinterpret_cast<const float4*>(in + (size_t)(c4 * 4 + 3) * HS * WS);
        *reinterpret_cast<float4*>(out + 0 * NC + c4 * 4) = make_float4(L0.x, L1.x, L2.x, L3.x);
        *reinterpret_cast<float4*>(out + 1 * NC + c4 * 4) = make_float4(L0.y, L1.y, L2.y, L3.y);
        *reinterpret_cast<float4*>(out + 2 * NC + c4 * 4) = make_float4(L0.z, L1.z, L2.z, L3.z);
        *reinterpret_cast<float4*>(out + 3 * NC + c4 * 4) = make_float4(L0.w, L1.w, L2.w, L3.w);
    }
}

// ---------------------------------------------------------------------------
// Kernel 3: per-(view,depth,pixel) bilinear weights + 4 absolute tap offsets
// ---------------------------------------------------------------------------
__global__ void coord_kernel(const float* __restrict__ nearfar)
{
    int t = blockIdx.x * blockDim.x + threadIdx.x;
    if (t >= NV * ND * NPIX) return;
    int pix = t & (NPIX - 1);
    int vd = t >> 14;
    int d = vd % ND;
    int v = vd / ND;

    float nearv = nearfar[pix];
    float farv  = nearfar[NPIX + pix];
    float depth = fmaf((farv - nearv) * (1.0f / (ND - 1)), (float)d, nearv);
    int x = pix & (WT - 1);
    int y = pix >> 7;
    float X = (float)x + 0.5f;
    float Y = (float)y + 0.5f;

    const float* P = d_proj + v * 12;
    float px_ = fmaf(fmaf(P[0], X, fmaf(P[1], Y, P[2])), depth, P[3]);
    float py_ = fmaf(fmaf(P[4], X, fmaf(P[5], Y, P[6])), depth, P[7]);
    float pz_ = fmaf(fmaf(P[8], X, fmaf(P[9], Y, P[10])), depth, P[11]);
    pz_ = fmaxf(pz_, 1e-6f);
    float gx = px_ / pz_ - 0.5f;
    float gy = py_ / pz_ - 0.5f;
    gx = fminf(fmaxf(gx, -1.0e6f), 1.0e6f);
    gy = fminf(fmaxf(gy, -1.0e6f), 1.0e6f);
    float x0f = floorf(gx), y0f = floorf(gy);
    float wx = gx - x0f, wy = gy - y0f;
    int x0 = (int)x0f, y0 = (int)y0f;
    int x1 = x0 + 1, y1 = y0 + 1;
    float w00 = (1.f - wy) * (1.f - wx);
    float w01 = (1.f - wy) * wx;
    float w10 = wy * (1.f - wx);
    float w11 = wy * wx;
    bool vx0 = ((unsigned)x0 < WS);
    bool vx1 = ((unsigned)x1 < WS);
    bool vy0 = ((unsigned)y0 < HS);
    bool vy1 = ((unsigned)y1 < HS);
    if (!(vy0 & vx0)) w00 = 0.f;
    if (!(vy0 & vx1)) w01 = 0.f;
    if (!(vy1 & vx0)) w10 = 0.f;
    if (!(vy1 & vx1)) w11 = 0.f;
    int cx0 = min(max(x0, 0), WS - 1);
    int cy0 = min(max(y0, 0), HS - 1);
    int cx1 = min(max(x1, 0), WS - 1);
    int cy1 = min(max(y1, 0), HS - 1);

    const int vb = v * (HS * WS * NC * 4);
    int4 offs;
    offs.x = vb + (cy0 * WS + cx0) * (NC * 4);
    offs.y = vb + (cy0 * WS + cx1) * (NC * 4);
    offs.z = vb + (cy1 * WS + cx0) * (NC * 4);
    offs.w = vb + (cy1 * WS + cx1) * (NC * 4);

    d_wgt[t] = make_float4(w00, w01, w10, w11);
    d_off4[t] = offs;
}

// ---------------------------------------------------------------------------
// Kernel 4: cost volume. Block = 32 pixels x 8-depth chunk (grid 512x6).
// Warp = 4 pixels x 8 channel-groups (float4). Views sequential; metadata
// loads have static addresses -> ptxas hoists across the unrolled depth loop.
// ---------------------------------------------------------------------------
__device__ __forceinline__ void accum_view(const char* fbase, const float4 W,
                                           const int4 O, float4& s1, float& S2)
{
    const float4 t00 = *reinterpret_cast<const float4*>(fbase + O.x);
    const float4 t01 = *reinterpret_cast<const float4*>(fbase + O.y);
    const float4 t10 = *reinterpret_cast<const float4*>(fbase + O.z);
    const float4 t11 = *reinterpret_cast<const float4*>(fbase + O.w);
    float4 wv;
    wv.x = fmaf(W.x, t00.x, fmaf(W.y, t01.x, fmaf(W.z, t10.x, W.w * t11.x)));
    wv.y = fmaf(W.x, t00.y, fmaf(W.y, t01.y, fmaf(W.z, t10.y, W.w * t11.y)));
    wv.z = fmaf(W.x, t00.z, fmaf(W.y, t01.z, fmaf(W.z, t10.z, W.w * t11.z)));
    wv.w = fmaf(W.x, t00.w, fmaf(W.y, t01.w, fmaf(W.z, t10.w, W.w * t11.w)));
    s1.x += wv.x; s1.y += wv.y; s1.z += wv.z; s1.w += wv.w;
    S2 = fmaf(wv.x, wv.x, S2);
    S2 = fmaf(wv.y, wv.y, S2);
    S2 = fmaf(wv.z, wv.z, S2);
    S2 = fmaf(wv.w, wv.w, S2);
}

__global__ void __launch_bounds__(256, 4)
cost_kernel()
{
    const int lane = threadIdx.x & 31;
    const int w    = threadIdx.x >> 5;
    const int cg   = lane & 7;
    const int pxl  = lane >> 3;
    const int pix  = blockIdx.x * 32 + w * 4 + pxl;
    const int d0   = blockIdx.y * 8;

    const char* fbase = (const char*)d_featT + cg * 16;
    const int m0 = d0 * NPIX + pix;

#pragma unroll
    for (int dd = 0; dd < 8; dd++) {
        const int m = m0 + dd * NPIX;
        float4 s1 = make_float4(0.f, 0.f, 0.f, 0.f);
        float S2 = 0.f;
        accum_view(fbase, d_wgt[m],               d_off4[m],               s1, S2);
        accum_view(fbase, d_wgt[m + VSTRIDE],     d_off4[m + VSTRIDE],     s1, S2);
        accum_view(fbase, d_wgt[m + 2 * VSTRIDE], d_off4[m + 2 * VSTRIDE], s1, S2);

        float q = fmaf(s1.x, s1.x, fmaf(s1.y, s1.y, fmaf(s1.z, s1.z, s1.w * s1.w)));
#pragma unroll
        for (int off = 1; off < 8; off <<= 1) {
            q  += __shfl_xor_sync(0xffffffffu, q, off);
            S2 += __shfl_xor_sync(0xffffffffu, S2, off);
        }
        if (cg == 0)
            d_cost[(d0 + dd) * NPIX + pix] =
                S2 * (1.0f / (NV * NC)) - q * (1.0f / (NV * NV * NC));
    }
}

// ---------------------------------------------------------------------------
// Kernel 5: softmax over depth -> expected depth, CI
// ---------------------------------------------------------------------------
__global__ void depth_kernel(const float* __restrict__ nearfar, float* __restrict__ out)
{
    int pix = blockIdx.x * blockDim.x + threadIdx.x;
    if (pix >= NPIX) return;
    const float nearv = nearfar[pix];
    const float farv  = nearfar[NPIX + pix];
    const float step  = (farv - nearv) * (1.0f / (ND - 1));

    float c[ND];
    float m = -1e30f;
#pragma unroll
    for (int d = 0; d < ND; d++) {
        c[d] = -d_cost[d * NPIX + pix];
        m = fmaxf(m, c[d]);
    }
    float Z = 0.f, S1 = 0.f;
#pragma unroll
    for (int d = 0; d < ND; d++) {
        float e = expf(c[d] - m);
        c[d] = e;
        Z += e;
        S1 = fmaf(e, fmaf(step, (float)d, nearv), S1);
    }
    const float invZ = 1.0f / Z;
    const float depth = S1 * invZ;
    float Svar = 0.f;
#pragma unroll
    for (int d = 0; d < ND; d++) {
        float dv = fmaf(step, (float)d, nearv);
        float diff = dv - depth;
        Svar = fmaf(c[d], diff * diff, Svar);
    }
    float var = Svar * invZ;
    float hc = sqrtf(fmaxf(var, 1e-12f));
    out[pix] = depth;
    out[NPIX + pix] = fmaxf(depth - hc, nearv);
    out[2 * NPIX + pix] = fminf(depth + hc, farv);
}

// ---------------------------------------------------------------------------
extern "C" void kernel_launch(void* const* d_in, const int* in_sizes, int n_in,
                              void* d_out, int out_size)
{
    const float* src_feat = (const float*)d_in[0];
    const float* src_exts = (const float*)d_in[1];
    const float* src_ints = (const float*)d_in[2];
    const float* tar_exts = (const float*)d_in[3];
    const float* tar_ints = (const float*)d_in[4];
    const float* near_far = (const float*)d_in[5];
    (void)in_sizes; (void)n_in; (void)out_size;

    setup_kernel<<<1, 32>>>(src_exts, src_ints, tar_exts, tar_ints);

    coord_kernel<<<(NV * ND * NPIX + 255) / 256, 256>>>(near_far);

    transpose_kernel<<<(NV * HS * WS / 4 + 255) / 256, 256>>>(src_feat);

    dim3 cg(NPIX / 32, ND / 8);
    cost_kernel<<<cg, 256>>>();

    depth_kernel<<<(NPIX + 127) / 128, 128>>>(near_far, (float*)d_out);
}

// round 5
// speedup vs baseline: 1.2728x; 1.2728x over previous
#include <cuda_runtime.h>
#include <math.h>

#define HT 128
#define WT 128
#define HS 256
#define WS 256
#define NC 32
#define NV 3
#define ND 48
#define NPIX (HT * WT)

// Static scratch (no allocs allowed)
__device__ float  d_featT[NV * HS * WS * NC];   // (v,y,x,c) channel-last, ~25MB
__device__ float4 d_wgt[NV * ND * NPIX];        // bilinear weights w00,w01,w10,w11
__device__ int    d_off[NV * ND * NPIX];        // packed base offset + step flags
__device__ float  d_cost[ND * NPIX];            // cost volume (d, pix)
__device__ float  d_proj[NV * 12];

// ---------------------------------------------------------------------------
// Kernel 1: projection matrices  proj_v = (Ks_v E_v[:3,:]) inv([Kt Et[:3,:];0001])
// ---------------------------------------------------------------------------
__global__ void setup_kernel(const float* __restrict__ src_exts,
                             const float* __restrict__ src_ints,
                             const float* __restrict__ tar_exts,
                             const float* __restrict__ tar_ints)
{
    if (threadIdx.x != 0) return;
    double T[4][4], inv[4][4];
    for (int i = 0; i < 3; i++)
        for (int j = 0; j < 4; j++) {
            double s = 0.0;
            for (int k = 0; k < 3; k++)
                s += (double)tar_ints[i * 3 + k] * (double)tar_exts[k * 4 + j];
            T[i][j] = s;
        }
    T[3][0] = 0.0; T[3][1] = 0.0; T[3][2] = 0.0; T[3][3] = 1.0;
    for (int i = 0; i < 4; i++)
        for (int j = 0; j < 4; j++) inv[i][j] = (i == j) ? 1.0 : 0.0;
    for (int col = 0; col < 4; col++) {
        int piv = col; double best = fabs(T[col][col]);
        for (int r = col + 1; r < 4; r++) {
            double a = fabs(T[r][col]);
            if (a > best) { best = a; piv = r; }
        }
        if (piv != col)
            for (int j = 0; j < 4; j++) {
                double t = T[col][j]; T[col][j] = T[piv][j]; T[piv][j] = t;
                t = inv[col][j]; inv[col][j] = inv[piv][j]; inv[piv][j] = t;
            }
        double p = 1.0 / T[col][col];
        for (int j = 0; j < 4; j++) { T[col][j] *= p; inv[col][j] *= p; }
        for (int r = 0; r < 4; r++)
            if (r != col) {
                double f = T[r][col];
                for (int j = 0; j < 4; j++) {
                    T[r][j] -= f * T[col][j];
                    inv[r][j] -= f * inv[col][j];
                }
            }
    }
    for (int v = 0; v < NV; v++) {
        const float* K = src_ints + v * 9;
        const float* E = src_exts + v * 16;
        double A[3][4];
        for (int i = 0; i < 3; i++)
            for (int j = 0; j < 4; j++) {
                double s = 0.0;
                for (int k = 0; k < 3; k++)
                    s += (double)K[i * 3 + k] * (double)E[k * 4 + j];
                A[i][j] = s;
            }
        for (int i = 0; i < 3; i++)
            for (int j = 0; j < 4; j++) {
                double s = 0.0;
                for (int k = 0; k < 4; k++) s += A[i][k] * inv[k][j];
                d_proj[v * 12 + i * 4 + j] = (float)s;
            }
    }
}

// ---------------------------------------------------------------------------
// Kernel 2: transpose (V,C,H,W) -> (V,H,W,C): one tap = one 128B line
// (R3-proven version)
// ---------------------------------------------------------------------------
__global__ void transpose_kernel(const float* __restrict__ src)
{
    int idx = blockIdx.x * blockDim.x + threadIdx.x;
    if (idx >= NV * HS * WS) return;
    int v = idx >> 16;
    int y = (idx >> 8) & (HS - 1);
    int x = idx & (WS - 1);
    const float* in = src + ((size_t)(v * NC) * HS + y) * WS + x;
    float buf[NC];
#pragma unroll
    for (int c = 0; c < NC; c++) buf[c] = in[(size_t)c * HS * WS];
    float4* out = reinterpret_cast<float4*>(d_featT + (size_t)idx * NC);
#pragma unroll
    for (int c4 = 0; c4 < NC / 4; c4++)
        out[c4] = make_float4(buf[c4 * 4], buf[c4 * 4 + 1], buf[c4 * 4 + 2], buf[c4 * 4 + 3]);
}

// ---------------------------------------------------------------------------
// Kernel 3: per-(view,depth,pixel) bilinear weights + packed tap offset
// word = byteoff(a00) | (x-step << 24) | (y-step << 25)
// ---------------------------------------------------------------------------
__global__ void coord_kernel(const float* __restrict__ nearfar)
{
    int t = blockIdx.x * blockDim.x + threadIdx.x;
    if (t >= NV * ND * NPIX) return;
    int pix = t & (NPIX - 1);
    int vd = t >> 14;
    int d = vd % ND;
    int v = vd / ND;

    float nearv = nearfar[pix];
    float farv  = nearfar[NPIX + pix];
    float depth = fmaf((farv - nearv) * (1.0f / (ND - 1)), (float)d, nearv);
    int x = pix & (WT - 1);
    int y = pix >> 7;
    float X = (float)x + 0.5f;
    float Y = (float)y + 0.5f;

    const float* P = d_proj + v * 12;
    float px_ = fmaf(fmaf(P[0], X, fmaf(P[1], Y, P[2])), depth, P[3]);
    float py_ = fmaf(fmaf(P[4], X, fmaf(P[5], Y, P[6])), depth, P[7]);
    float pz_ = fmaf(fmaf(P[8], X, fmaf(P[9], Y, P[10])), depth, P[11]);
    pz_ = fmaxf(pz_, 1e-6f);
    float gx = px_ / pz_ - 0.5f;
    float gy = py_ / pz_ - 0.5f;
    gx = fminf(fmaxf(gx, -1.0e6f), 1.0e6f);
    gy = fminf(fmaxf(gy, -1.0e6f), 1.0e6f);
    float x0f = floorf(gx), y0f = floorf(gy);
    float wx = gx - x0f, wy = gy - y0f;
    int x0 = (int)x0f, y0 = (int)y0f;
    int x1 = x0 + 1, y1 = y0 + 1;
    float w00 = (1.f - wy) * (1.f - wx);
    float w01 = (1.f - wy) * wx;
    float w10 = wy * (1.f - wx);
    float w11 = wy * wx;
    bool vx0 = ((unsigned)x0 < WS);
    bool vx1 = ((unsigned)x1 < WS);
    bool vy0 = ((unsigned)y0 < HS);
    bool vy1 = ((unsigned)y1 < HS);
    if (!(vy0 & vx0)) w00 = 0.f;
    if (!(vy0 & vx1)) w01 = 0.f;
    if (!(vy1 & vx0)) w10 = 0.f;
    if (!(vy1 & vx1)) w11 = 0.f;
    int cx0 = min(max(x0, 0), WS - 1);
    int cy0 = min(max(y0, 0), HS - 1);
    int cx1 = min(max(x1, 0), WS - 1);
    int cy1 = min(max(y1, 0), HS - 1);

    int a00 = (cy0 * WS + cx0) * (NC * 4);
    int word = a00 | ((cx1 - cx0) << 24) | ((cy1 - cy0) << 25);

    d_wgt[t] = make_float4(w00, w01, w10, w11);
    d_off[t] = word;
}

// ---------------------------------------------------------------------------
// Kernel 4: cost volume. Block = 32 pixels x 8-depth chunk (grid 512x6).
// Metadata for the whole block staged in SMEM up front -> the depth loop's
// only global-latency ops are the (highly parallel) tap loads.
// ---------------------------------------------------------------------------
__global__ void __launch_bounds__(256, 4)
cost_kernel()
{
    __shared__ float4 s_wgt[8][NV][32];
    __shared__ int    s_word[8][NV][32];

    const int tid  = threadIdx.x;
    const int pix0 = blockIdx.x * 32;
    const int d0   = blockIdx.y * 8;

    // Bulk metadata prefetch: 768 entries, coalesced, MLP=3 per thread
#pragma unroll
    for (int e = tid; e < 8 * NV * 32; e += 256) {
        const int p  = e & 31;
        const int v  = (e >> 5) % NV;
        const int dd = e / (NV * 32);
        const int g  = (v * ND + d0 + dd) * NPIX + pix0 + p;
        s_wgt[dd][v][p]  = d_wgt[g];
        s_word[dd][v][p] = d_off[g];
    }
    __syncthreads();

    const int lane = tid & 31;
    const int w    = tid >> 5;
    const int cg   = lane & 7;
    const int pxl  = lane >> 3;
    const int pl   = w * 4 + pxl;            // pixel within block 0..31
    const int pix  = pix0 + pl;

    const char* fbase = (const char*)d_featT + cg * 16;

#pragma unroll
    for (int dd = 0; dd < 8; dd++) {
        float4 s1 = make_float4(0.f, 0.f, 0.f, 0.f);
        float S2 = 0.f;
#pragma unroll
        for (int v = 0; v < NV; v++) {
            const float4 W   = s_wgt[dd][v][pl];    // LDS broadcast across cg
            const int   word = s_word[dd][v][pl];
            const char* base = fbase + (size_t)v * (HS * WS * NC * 4) + (word & 0xFFFFFF);
            const int dx = (word >> 17) & 128;      // bit24 -> 128 B
            const int dy = (word >> 10) & 32768;    // bit25 -> 32768 B

            const float4 t00 = *reinterpret_cast<const float4*>(base);
            const float4 t01 = *reinterpret_cast<const float4*>(base + dx);
            const float4 t10 = *reinterpret_cast<const float4*>(base + dy);
            const float4 t11 = *reinterpret_cast<const float4*>(base + dy + dx);

            float4 wv;
            wv.x = fmaf(W.x, t00.x, fmaf(W.y, t01.x, fmaf(W.z, t10.x, W.w * t11.x)));
            wv.y = fmaf(W.x, t00.y, fmaf(W.y, t01.y, fmaf(W.z, t10.y, W.w * t11.y)));
            wv.z = fmaf(W.x, t00.z, fmaf(W.y, t01.z, fmaf(W.z, t10.z, W.w * t11.z)));
            wv.w = fmaf(W.x, t00.w, fmaf(W.y, t01.w, fmaf(W.z, t10.w, W.w * t11.w)));

            s1.x += wv.x; s1.y += wv.y; s1.z += wv.z; s1.w += wv.w;
            S2 = fmaf(wv.x, wv.x, S2);
            S2 = fmaf(wv.y, wv.y, S2);
            S2 = fmaf(wv.z, wv.z, S2);
            S2 = fmaf(wv.w, wv.w, S2);
        }

        float q = fmaf(s1.x, s1.x, fmaf(s1.y, s1.y, fmaf(s1.z, s1.z, s1.w * s1.w)));
#pragma unroll
        for (int off = 1; off < 8; off <<= 1) {
            q  += __shfl_xor_sync(0xffffffffu, q, off);
            S2 += __shfl_xor_sync(0xffffffffu, S2, off);
        }
        if (cg == 0)
            d_cost[(d0 + dd) * NPIX + pix] =
                S2 * (1.0f / (NV * NC)) - q * (1.0f / (NV * NV * NC));
    }
}

// ---------------------------------------------------------------------------
// Kernel 5: softmax over depth -> expected depth, CI
// ---------------------------------------------------------------------------
__global__ void depth_kernel(const float* __restrict__ nearfar, float* __restrict__ out)
{
    int pix = blockIdx.x * blockDim.x + threadIdx.x;
    if (pix >= NPIX) return;
    const float nearv = nearfar[pix];
    const float farv  = nearfar[NPIX + pix];
    const float step  = (farv - nearv) * (1.0f / (ND - 1));

    float c[ND];
    float m = -1e30f;
#pragma unroll
    for (int d = 0; d < ND; d++) {
        c[d] = -d_cost[d * NPIX + pix];
        m = fmaxf(m, c[d]);
    }
    float Z = 0.f, S1 = 0.f;
#pragma unroll
    for (int d = 0; d < ND; d++) {
        float e = expf(c[d] - m);
        c[d] = e;
        Z += e;
        S1 = fmaf(e, fmaf(step, (float)d, nearv), S1);
    }
    const float invZ = 1.0f / Z;
    const float depth = S1 * invZ;
    float Svar = 0.f;
#pragma unroll
    for (int d = 0; d < ND; d++) {
        float dv = fmaf(step, (float)d, nearv);
        float diff = dv - depth;
        Svar = fmaf(c[d], diff * diff, Svar);
    }
    float var = Svar * invZ;
    float hc = sqrtf(fmaxf(var, 1e-12f));
    out[pix] = depth;
    out[NPIX + pix] = fmaxf(depth - hc, nearv);
    out[2 * NPIX + pix] = fminf(depth + hc, farv);
}

// ---------------------------------------------------------------------------
extern "C" void kernel_launch(void* const* d_in, const int* in_sizes, int n_in,
                              void* d_out, int out_size)
{
    const float* src_feat = (const float*)d_in[0];
    const float* src_exts = (const float*)d_in[1];
    const float* src_ints = (const float*)d_in[2];
    const float* tar_exts = (const float*)d_in[3];
    const float* tar_ints = (const float*)d_in[4];
    const float* near_far = (const float*)d_in[5];
    (void)in_sizes; (void)n_in; (void)out_size;

    setup_kernel<<<1, 32>>>(src_exts, src_ints, tar_exts, tar_ints);

    transpose_kernel<<<(NV * HS * WS + 255) / 256, 256>>>(src_feat);

    coord_kernel<<<(NV * ND * NPIX + 255) / 256, 256>>>(near_far);

    dim3 cg(NPIX / 32, ND / 8);
    cost_kernel<<<cg, 256>>>();

    depth_kernel<<<(NPIX + 127) / 128, 128>>>(near_far, (float*)d_out);
}

// round 6
// speedup vs baseline: 1.4024x; 1.1019x over previous
#include <cuda_runtime.h>
#include <math.h>

#define HT 128
#define WT 128
#define HS 256
#define WS 256
#define NC 32
#define NV 3
#define ND 48
#define NPIX (HT * WT)

// Static scratch (no allocs allowed)
__device__ float  d_featT[NV * HS * WS * NC];   // (v,y,x,c) channel-last, ~25MB
__device__ float  d_cost[ND * NPIX];            // cost volume (d, pix)
__device__ float  d_proj[NV * 12];

// ---------------------------------------------------------------------------
// Kernel 1: projection matrices  proj_v = (Ks_v E_v[:3,:]) inv([Kt Et[:3,:];0001])
// ---------------------------------------------------------------------------
__global__ void setup_kernel(const float* __restrict__ src_exts,
                             const float* __restrict__ src_ints,
                             const float* __restrict__ tar_exts,
                             const float* __restrict__ tar_ints)
{
    if (threadIdx.x != 0) return;
    double T[4][4], inv[4][4];
    for (int i = 0; i < 3; i++)
        for (int j = 0; j < 4; j++) {
            double s = 0.0;
            for (int k = 0; k < 3; k++)
                s += (double)tar_ints[i * 3 + k] * (double)tar_exts[k * 4 + j];
            T[i][j] = s;
        }
    T[3][0] = 0.0; T[3][1] = 0.0; T[3][2] = 0.0; T[3][3] = 1.0;
    for (int i = 0; i < 4; i++)
        for (int j = 0; j < 4; j++) inv[i][j] = (i == j) ? 1.0 : 0.0;
    for (int col = 0; col < 4; col++) {
        int piv = col; double best = fabs(T[col][col]);
        for (int r = col + 1; r < 4; r++) {
            double a = fabs(T[r][col]);
            if (a > best) { best = a; piv = r; }
        }
        if (piv != col)
            for (int j = 0; j < 4; j++) {
                double t = T[col][j]; T[col][j] = T[piv][j]; T[piv][j] = t;
                t = inv[col][j]; inv[col][j] = inv[piv][j]; inv[piv][j] = t;
            }
        double p = 1.0 / T[col][col];
        for (int j = 0; j < 4; j++) { T[col][j] *= p; inv[col][j] *= p; }
        for (int r = 0; r < 4; r++)
            if (r != col) {
                double f = T[r][col];
                for (int j = 0; j < 4; j++) {
                    T[r][j] -= f * T[col][j];
                    inv[r][j] -= f * inv[col][j];
                }
            }
    }
    for (int v = 0; v < NV; v++) {
        const float* K = src_ints + v * 9;
        const float* E = src_exts + v * 16;
        double A[3][4];
        for (int i = 0; i < 3; i++)
            for (int j = 0; j < 4; j++) {
                double s = 0.0;
                for (int k = 0; k < 3; k++)
                    s += (double)K[i * 3 + k] * (double)E[k * 4 + j];
                A[i][j] = s;
            }
        for (int i = 0; i < 3; i++)
            for (int j = 0; j < 4; j++) {
                double s = 0.0;
                for (int k = 0; k < 4; k++) s += A[i][k] * inv[k][j];
                d_proj[v * 12 + i * 4 + j] = (float)s;
            }
    }
}

// ---------------------------------------------------------------------------
// Kernel 2: transpose (V,C,H,W) -> (V,H,W,C): one tap = one 128B line
// ---------------------------------------------------------------------------
__global__ void transpose_kernel(const float* __restrict__ src)
{
    int idx = blockIdx.x * blockDim.x + threadIdx.x;
    if (idx >= NV * HS * WS) return;
    int v = idx >> 16;
    int y = (idx >> 8) & (HS - 1);
    int x = idx & (WS - 1);
    const float* in = src + ((size_t)(v * NC) * HS + y) * WS + x;
    float buf[NC];
#pragma unroll
    for (int c = 0; c < NC; c++) buf[c] = in[(size_t)c * HS * WS];
    float4* out = reinterpret_cast<float4*>(d_featT + (size_t)idx * NC);
#pragma unroll
    for (int c4 = 0; c4 < NC / 4; c4++)
        out[c4] = make_float4(buf[c4 * 4], buf[c4 * 4 + 1], buf[c4 * 4 + 2], buf[c4 * 4 + 3]);
}

// ---------------------------------------------------------------------------
// Kernel 3: cost volume with INLINE distributed coordinate computation.
// Block = 32 pixels x 8 depths. Staging phase: 256 threads compute the 768
// (pixel,depth,view) projections (3 each) directly into SMEM. Main loop
// unchanged from R5 (proven): LDS metadata + 12 parallel tap loads per depth.
// ---------------------------------------------------------------------------
__global__ void __launch_bounds__(256, 4)
cost_kernel(const float* __restrict__ nearfar)
{
    __shared__ float4 s_wgt[8][NV][32];
    __shared__ int    s_word[8][NV][32];

    const int tid  = threadIdx.x;
    const int pix0 = blockIdx.x * 32;
    const int d0   = blockIdx.y * 8;

    // ---- staging: each thread computes 3 coord tasks (one per view) ----
#pragma unroll
    for (int e = tid; e < 8 * NV * 32; e += 256) {
        const int p  = e & 31;
        const int v  = (e >> 5) % NV;
        const int dd = e / (NV * 32);
        const int pix = pix0 + p;
        const int d   = d0 + dd;

        const float nearv = nearfar[pix];
        const float farv  = nearfar[NPIX + pix];
        const float depth = fmaf((farv - nearv) * (1.0f / (ND - 1)), (float)d, nearv);
        const int x = pix & (WT - 1);
        const int y = pix >> 7;
        const float X = (float)x + 0.5f;
        const float Y = (float)y + 0.5f;

        const float* P = d_proj + v * 12;
        float px_ = fmaf(fmaf(P[0], X, fmaf(P[1], Y, P[2])), depth, P[3]);
        float py_ = fmaf(fmaf(P[4], X, fmaf(P[5], Y, P[6])), depth, P[7]);
        float pz_ = fmaf(fmaf(P[8], X, fmaf(P[9], Y, P[10])), depth, P[11]);
        pz_ = fmaxf(pz_, 1e-6f);
        float gx = px_ / pz_ - 0.5f;
        float gy = py_ / pz_ - 0.5f;
        gx = fminf(fmaxf(gx, -1.0e6f), 1.0e6f);
        gy = fminf(fmaxf(gy, -1.0e6f), 1.0e6f);
        float x0f = floorf(gx), y0f = floorf(gy);
        float wx = gx - x0f, wy = gy - y0f;
        int x0 = (int)x0f, y0 = (int)y0f;
        int x1 = x0 + 1, y1 = y0 + 1;
        float w00 = (1.f - wy) * (1.f - wx);
        float w01 = (1.f - wy) * wx;
        float w10 = wy * (1.f - wx);
        float w11 = wy * wx;
        bool vx0 = ((unsigned)x0 < WS);
        bool vx1 = ((unsigned)x1 < WS);
        bool vy0 = ((unsigned)y0 < HS);
        bool vy1 = ((unsigned)y1 < HS);
        if (!(vy0 & vx0)) w00 = 0.f;
        if (!(vy0 & vx1)) w01 = 0.f;
        if (!(vy1 & vx0)) w10 = 0.f;
        if (!(vy1 & vx1)) w11 = 0.f;
        int cx0 = min(max(x0, 0), WS - 1);
        int cy0 = min(max(y0, 0), HS - 1);
        int cx1 = min(max(x1, 0), WS - 1);
        int cy1 = min(max(y1, 0), HS - 1);

        int a00 = (cy0 * WS + cx0) * (NC * 4);
        s_wgt[dd][v][p]  = make_float4(w00, w01, w10, w11);
        s_word[dd][v][p] = a00 | ((cx1 - cx0) << 24) | ((cy1 - cy0) << 25);
    }
    __syncthreads();

    // ---- main loop (R5-proven) ----
    const int lane = tid & 31;
    const int w    = tid >> 5;
    const int cg   = lane & 7;
    const int pxl  = lane >> 3;
    const int pl   = w * 4 + pxl;
    const int pix  = pix0 + pl;

    const char* fbase = (const char*)d_featT + cg * 16;

#pragma unroll
    for (int dd = 0; dd < 8; dd++) {
        float4 s1 = make_float4(0.f, 0.f, 0.f, 0.f);
        float S2 = 0.f;
#pragma unroll
        for (int v = 0; v < NV; v++) {
            const float4 W   = s_wgt[dd][v][pl];
            const int   word = s_word[dd][v][pl];
            const char* base = fbase + (size_t)v * (HS * WS * NC * 4) + (word & 0xFFFFFF);
            const int dx = (word >> 17) & 128;      // bit24 -> 128 B
            const int dy = (word >> 10) & 32768;    // bit25 -> 32768 B

            const float4 t00 = *reinterpret_cast<const float4*>(base);
            const float4 t01 = *reinterpret_cast<const float4*>(base + dx);
            const float4 t10 = *reinterpret_cast<const float4*>(base + dy);
            const float4 t11 = *reinterpret_cast<const float4*>(base + dy + dx);

            float4 wv;
            wv.x = fmaf(W.x, t00.x, fmaf(W.y, t01.x, fmaf(W.z, t10.x, W.w * t11.x)));
            wv.y = fmaf(W.x, t00.y, fmaf(W.y, t01.y, fmaf(W.z, t10.y, W.w * t11.y)));
            wv.z = fmaf(W.x, t00.z, fmaf(W.y, t01.z, fmaf(W.z, t10.z, W.w * t11.z)));
            wv.w = fmaf(W.x, t00.w, fmaf(W.y, t01.w, fmaf(W.z, t10.w, W.w * t11.w)));

            s1.x += wv.x; s1.y += wv.y; s1.z += wv.z; s1.w += wv.w;
            S2 = fmaf(wv.x, wv.x, S2);
            S2 = fmaf(wv.y, wv.y, S2);
            S2 = fmaf(wv.z, wv.z, S2);
            S2 = fmaf(wv.w, wv.w, S2);
        }

        float q = fmaf(s1.x, s1.x, fmaf(s1.y, s1.y, fmaf(s1.z, s1.z, s1.w * s1.w)));
#pragma unroll
        for (int off = 1; off < 8; off <<= 1) {
            q  += __shfl_xor_sync(0xffffffffu, q, off);
            S2 += __shfl_xor_sync(0xffffffffu, S2, off);
        }
        if (cg == 0)
            d_cost[(d0 + dd) * NPIX + pix] =
                S2 * (1.0f / (NV * NC)) - q * (1.0f / (NV * NV * NC));
    }
}

// ---------------------------------------------------------------------------
// Kernel 4: softmax over depth -> expected depth, CI
// ---------------------------------------------------------------------------
__global__ void depth_kernel(const float* __restrict__ nearfar, float* __restrict__ out)
{
    int pix = blockIdx.x * blockDim.x + threadIdx.x;
    if (pix >= NPIX) return;
    const float nearv = nearfar[pix];
    const float farv  = nearfar[NPIX + pix];
    const float step  = (farv - nearv) * (1.0f / (ND - 1));

    float c[ND];
    float m = -1e30f;
#pragma unroll
    for (int d = 0; d < ND; d++) {
        c[d] = -d_cost[d * NPIX + pix];
        m = fmaxf(m, c[d]);
    }
    float Z = 0.f, S1 = 0.f;
#pragma unroll
    for (int d = 0; d < ND; d++) {
        float e = expf(c[d] - m);
        c[d] = e;
        Z += e;
        S1 = fmaf(e, fmaf(step, (float)d, nearv), S1);
    }
    const float invZ = 1.0f / Z;
    const float depth = S1 * invZ;
    float Svar = 0.f;
#pragma unroll
    for (int d = 0; d < ND; d++) {
        float dv = fmaf(step, (float)d, nearv);
        float diff = dv - depth;
        Svar = fmaf(c[d], diff * diff, Svar);
    }
    float var = Svar * invZ;
    float hc = sqrtf(fmaxf(var, 1e-12f));
    out[pix] = depth;
    out[NPIX + pix] = fmaxf(depth - hc, nearv);
    out[2 * NPIX + pix] = fminf(depth + hc, farv);
}

// ---------------------------------------------------------------------------
extern "C" void kernel_launch(void* const* d_in, const int* in_sizes, int n_in,
                              void* d_out, int out_size)
{
    const float* src_feat = (const float*)d_in[0];
    const float* src_exts = (const float*)d_in[1];
    const float* src_ints = (const float*)d_in[2];
    const float* tar_exts = (const float*)d_in[3];
    const float* tar_ints = (const float*)d_in[4];
    const float* near_far = (const float*)d_in[5];
    (void)in_sizes; (void)n_in; (void)out_size;

    setup_kernel<<<1, 32>>>(src_exts, src_ints, tar_exts, tar_ints);

    transpose_kernel<<<(NV * HS * WS + 255) / 256, 256>>>(src_feat);

    dim3 cg(NPIX / 32, ND / 8);
    cost_kernel<<<cg, 256>>>(near_far);

    depth_kernel<<<(NPIX + 127) / 128, 128>>>(near_far, (float*)d_out);
}